// round 8
// baseline (speedup 1.0000x reference)
#include <cuda_runtime.h>
#include <math.h>

// Problem constants
#define SEQQ   1024      // L_SIDE*L_SIDE
#define BSZ    8
#define EMBED  1024
#define KDIM   64        // kernel_dim = DIRS * N_SSM
#define NDIM   16
#define VPOW   64        // vander power dim
#define R2E    16        // expansion terms per position
#define NR     16384     // R per flow axis (SEQ * R2)
#define HCH    64        // EMBED / N_SSM

// ---------------- scratch (device globals; no allocations) ----------------
__device__ float g_Ls[4 * 1024];        // log2(sigmoid(A))  [a][kd*16+n]
__device__ float g_Bsig[2 * 1024];      // sigmoid(B1/B2)    [c][kd*16+n]
__device__ int   g_E[2 * NR * 4];       // one-hot power indices per (d,r,a)
__device__ int   g_Col[2 * NR];         // B column select (0/1)
__device__ float g_Coef[2 * NR];        // integer coefficient
__device__ float g_w[SEQQ * KDIM * 32]; // w  [p][kd][dn] , dn = d*16+n
__device__ float g_Cc[KDIM * HCH * 32]; // Ccat [kd][h][dn] (x0.25 folded)
__device__ float g_ktmp[HCH * KDIM * SEQQ]; // [h][kd][p]
__device__ float g_kdup[EMBED * 2048];  // duplicated kernel [e][di][2*dj] = (k,k)

// ---------------- f32x2 packed helpers ----------------
__device__ __forceinline__ unsigned long long pack2(float a, float b) {
    unsigned long long r;
    asm("mov.b64 %0, {%1,%2};" : "=l"(r) : "f"(a), "f"(b));
    return r;
}
__device__ __forceinline__ void unpack2(float& a, float& b, unsigned long long v) {
    asm("mov.b64 {%0,%1}, %2;" : "=f"(a), "=f"(b) : "l"(v));
}
__device__ __forceinline__ unsigned long long fma2(unsigned long long a,
                                                   unsigned long long b,
                                                   unsigned long long c) {
    unsigned long long d;
    asm("fma.rn.f32x2 %0, %1, %2, %3;" : "=l"(d) : "l"(a), "l"(b), "l"(c));
    return d;
}
__device__ __forceinline__ unsigned long long mul2(unsigned long long a,
                                                   unsigned long long b) {
    unsigned long long d;
    asm("mul.rn.f32x2 %0, %1, %2;" : "=l"(d) : "l"(a), "l"(b));
    return d;
}

// ---------------- stage 1: sigmoids / logs / Ccat ----------------
__global__ void k_prep(const float* __restrict__ A,
                       const float* __restrict__ B1,
                       const float* __restrict__ B2,
                       const float* __restrict__ C1,
                       const float* __restrict__ C2) {
    int idx = blockIdx.x * blockDim.x + threadIdx.x;
    if (idx < 4096) {
        float s = 1.0f / (1.0f + expf(-A[idx]));    // A layout (4,64,16) linear
        g_Ls[idx] = log2f(s);
    } else if (idx < 5120) {
        int t = idx - 4096;
        g_Bsig[t] = 1.0f / (1.0f + expf(-B1[t]));
    } else if (idx < 6144) {
        int t = idx - 5120;
        g_Bsig[1024 + t] = 1.0f / (1.0f + expf(-B2[t]));
    }
    if (idx < KDIM * HCH * 32) {                    // 131072
        int kd = idx >> 11;            // /2048
        int hh = (idx >> 5) & 63;
        int dn = idx & 31;
        int d = dn >> 4, n = dn & 15;
        const float* C = d ? C2 : C1;
        g_Cc[idx] = 0.25f * C[(hh * 64 + kd) * 16 + n];   // scale=1/sqrt(16)
    }
}

// ---------------- stage 2: decode one_matrix (one-hot selectors) ----------------
__global__ void k_decode(const float* __restrict__ M) {
    int t = blockIdx.x * blockDim.x + threadIdx.x;   // (d,a,r) flattened
    if (t >= 2 * 5 * NR) return;
    const float4* m4 = reinterpret_cast<const float4*>(M + (size_t)t * 64);
    int idx = 0; float val = 0.0f;
#pragma unroll
    for (int i = 0; i < 16; i++) {
        float4 v = m4[i];
        if (v.x != 0.0f) { idx = 4 * i + 0; val = v.x; }
        if (v.y != 0.0f) { idx = 4 * i + 1; val = v.y; }
        if (v.z != 0.0f) { idx = 4 * i + 2; val = v.z; }
        if (v.w != 0.0f) { idx = 4 * i + 3; val = v.w; }
    }
    int d   = t / (5 * NR);
    int rem = t - d * (5 * NR);
    int a   = rem / NR;
    int r   = rem - a * NR;
    if (a < 4) {
        g_E[(d * NR + r) * 4 + a] = idx;
    } else {
        g_Col[d * NR + r]  = idx;     // 0 or 1
        g_Coef[d * NR + r] = val;
    }
}

// ---------------- stage 3: w[d,p,k,n] via exp2 of summed log-powers ----------------
__global__ void k_w() {
    __shared__ float se[64];
    __shared__ float scoef[16];
    __shared__ int   scol[16];
    int d = blockIdx.x >> 10;
    int p = blockIdx.x & 1023;
    int tid = threadIdx.x;
    if (tid < 64) {
        int r2 = tid >> 2, a = tid & 3;
        se[tid] = (float)g_E[(d * NR + p * 16 + r2) * 4 + a];
    } else if (tid < 80) {
        scoef[tid - 64] = g_Coef[d * NR + p * 16 + (tid - 64)];
    } else if (tid < 96) {
        scol[tid - 80] = g_Col[d * NR + p * 16 + (tid - 80)];
    }
    __syncthreads();
    int kn = tid;                       // 1024 threads = (kd,n)
    float ls0 = g_Ls[kn], ls1 = g_Ls[1024 + kn];
    float ls2 = g_Ls[2048 + kn], ls3 = g_Ls[3072 + kn];
    float b0 = g_Bsig[kn], b1 = g_Bsig[1024 + kn];
    float acc = 0.0f;
#pragma unroll
    for (int r2 = 0; r2 < 16; r2++) {
        float E = se[r2 * 4 + 0] * ls0 + se[r2 * 4 + 1] * ls1
                + se[r2 * 4 + 2] * ls2 + se[r2 * 4 + 3] * ls3;
        float term = exp2f(E) * scoef[r2] * (scol[r2] ? b1 : b0);
        acc += term;
    }
    g_w[(p * 64 + (kn >> 4)) * 32 + d * 16 + (kn & 15)] = acc;
}

// ---------------- stage 4: 64 small GEMMs -> ktmp[h][kd][p] ----------------
__global__ __launch_bounds__(256) void k_gemm() {
    __shared__ float Cs[2048];        // [h][dn]  (broadcast reads -> no pad)
    __shared__ float ws[64 * 33];     // [pl][dn] stride-33 pad
    int kd = blockIdx.x & 63;
    int p0 = (blockIdx.x >> 6) * 64;
    int tid = threadIdx.x;
    for (int idx = tid; idx < 2048; idx += 256)
        Cs[idx] = g_Cc[kd * 2048 + idx];
    for (int idx = tid; idx < 2048; idx += 256) {
        int pl = idx >> 5, dn = idx & 31;
        ws[pl * 33 + dn] = g_w[((size_t)(p0 + pl) * 64 + kd) * 32 + dn];
    }
    __syncthreads();
    int tp = tid & 31;                 // p = p0 + tp + 32*i  (bank-disjoint)
    int h0 = (tid >> 5) * 8;
    float acc[2][8];
#pragma unroll
    for (int i = 0; i < 2; i++)
#pragma unroll
        for (int j = 0; j < 8; j++) acc[i][j] = 0.0f;
#pragma unroll 8
    for (int dn = 0; dn < 32; dn++) {
        float cv[8];
#pragma unroll
        for (int j = 0; j < 8; j++) cv[j] = Cs[(h0 + j) * 32 + dn];
#pragma unroll
        for (int i = 0; i < 2; i++) {
            float wv = ws[(tp + 32 * i) * 33 + dn];
#pragma unroll
            for (int j = 0; j < 8; j++) acc[i][j] += wv * cv[j];
        }
    }
#pragma unroll
    for (int j = 0; j < 8; j++)
#pragma unroll
        for (int i = 0; i < 2; i++)
            g_ktmp[((h0 + j) * 64 + kd) * 1024 + p0 + tp + 32 * i] = acc[i][j];
}

// ---------------- stage 5: boundary scale + flip-sum -> duplicated pairs ----------------
__device__ __forceinline__ float bscale(int i, int j) {
    return ((i == 0) != (j == 0)) ? 2.0f : 1.0f;
}
__global__ void k_asm() {
    int e = blockIdx.x;
    int h = e >> 4, ns = e & 15;
    const float* b0 = g_ktmp + (h * 64 +  0 + ns) * 1024;
    const float* b1 = g_ktmp + (h * 64 + 16 + ns) * 1024;
    const float* b2 = g_ktmp + (h * 64 + 32 + ns) * 1024;
    const float* b3 = g_ktmp + (h * 64 + 48 + ns) * 1024;
    for (int pos = threadIdx.x; pos < 1024; pos += 256) {
        int i = pos >> 5, j = pos & 31;
        int fi = 31 - i, fj = 31 - j;
        float v = bscale(i,  j)  * b0[i  * 32 + j ]
                + bscale(fi, j)  * b1[fi * 32 + j ]
                + bscale(i,  fj) * b2[i  * 32 + fj]
                + bscale(fi, fj) * b3[fi * 32 + fj];
        // duplicated pair layout for FFMA2 operands: [e][di=i][2*dj + {0,1}]
        g_kdup[(size_t)e * 2048 + i * 64 + 2 * j]     = v;
        g_kdup[(size_t)e * 2048 + i * 64 + 2 * j + 1] = v;
    }
}

// ---------------- stage 6: causal 2D conv + residual (j-packed f32x2) ----------------
// Warp per image (b,e); lane l owns output row l as 16 packed f32x2 pairs.
// Even dj -> even-aligned source pairs xe[m-dj/2] (natural LDS.64 pairs).
// Odd  dj -> odd-aligned pairs xo[t]=(x[2t-1],x[2t]), xo[0]=(0,x[0]) absorbing
// the boundary tap exactly (0*k contributes nothing). 272 FFMA2 per shift
// vs 528 scalar FFMA. Kernel taps come pre-duplicated from g_kdup via
// uniform LDG.128 (no packing movs on hot path).
__global__ __launch_bounds__(256, 2) void k_conv(const float* __restrict__ x,
                                                 const float* __restrict__ omega,
                                                 float* __restrict__ out) {
    __shared__ __align__(16) float sx[8 * 1088];   // 8 channels, row stride 34
    int b  = blockIdx.x >> 7;
    int e0 = (blockIdx.x & 127) * 8;
    int tid = threadIdx.x;
    int ww = tid >> 5, lane = tid & 31;

    // coalesced staging of x (layout x[pos][b][e])
    for (int idx = tid; idx < 8192; idx += 256) {
        int pos = idx >> 3, ee = idx & 7;
        int row = pos >> 5, q = pos & 31;
        sx[ee * 1088 + row * 34 + q] = x[(size_t)(pos * 8 + b) * 1024 + e0 + ee];
    }
    __syncthreads();

    float* sxw = sx + ww * 1088;
    const float* kdup = g_kdup + (size_t)(e0 + ww) * 2048;
    float om = omega[e0 + ww];
    unsigned long long om2 = pack2(om, om);

    // residual init: y = om * own row (row stride 34 floats -> 8B aligned)
    unsigned long long y[16];
    {
        const unsigned long long* rp =
            reinterpret_cast<const unsigned long long*>(sxw + lane * 34);
#pragma unroll
        for (int m = 0; m < 16; m++) y[m] = mul2(om2, rp[m]);
    }

    for (int di = 0; di < 32; di++) {
        if (lane >= di) {
            int p = lane - di;
            unsigned long long xe[16];
            const unsigned long long* rp =
                reinterpret_cast<const unsigned long long*>(sxw + p * 34);
#pragma unroll
            for (int c = 0; c < 16; c++) xe[c] = rp[c];
            // odd-aligned pairs (hoisted; reused across all odd dj)
            unsigned long long xo[16];
            {
                float lo, hi, plo, phi;
                unpack2(lo, hi, xe[0]);
                xo[0] = pack2(0.0f, lo);
                plo = lo; phi = hi;
#pragma unroll
                for (int t = 1; t < 16; t++) {
                    unpack2(lo, hi, xe[t]);
                    xo[t] = pack2(phi, lo);
                    plo = lo; phi = hi;
                }
            }
#pragma unroll
            for (int ch = 0; ch < 4; ch++) {
                unsigned long long kd[8];
                const ulonglong2* kk =
                    reinterpret_cast<const ulonglong2*>(kdup + di * 64 + ch * 16);
#pragma unroll
                for (int c = 0; c < 4; c++) {
                    ulonglong2 v = kk[c];
                    kd[2 * c] = v.x; kd[2 * c + 1] = v.y;
                }
#pragma unroll
                for (int u = 0; u < 8; u++) {
                    const int dj = ch * 8 + u;
                    if ((dj & 1) == 0) {
                        const int h = dj >> 1;
#pragma unroll
                        for (int m = 0; m < 16; m++)
                            if (m >= h) y[m] = fma2(kd[u], xe[m - h], y[m]);
                    } else {
                        const int s = (dj + 1) >> 1;
#pragma unroll
                        for (int m = 0; m < 16; m++)
                            if (m >= s - 1) y[m] = fma2(kd[u], xo[m - s + 1], y[m]);
                    }
                }
            }
        }
    }

    // store own row back (aligned u64 stores, lanes 0-15/16-31 bank-disjoint)
    {
        unsigned long long* rp =
            reinterpret_cast<unsigned long long*>(sxw + lane * 34);
#pragma unroll
        for (int m = 0; m < 16; m++) rp[m] = y[m];
    }
    __syncthreads();

    // coalesced writeback to out[pos][b][e]
    for (int idx = tid; idx < 8192; idx += 256) {
        int pos = idx >> 3, ee = idx & 7;
        int row = pos >> 5, q = pos & 31;
        out[(size_t)(pos * 8 + b) * 1024 + e0 + ee] = sx[ee * 1088 + row * 34 + q];
    }
}

// ---------------- launch ----------------
extern "C" void kernel_launch(void* const* d_in, const int* in_sizes, int n_in,
                              void* d_out, int out_size) {
    const float* x     = (const float*)d_in[0];
    const float* A     = (const float*)d_in[1];
    const float* B1    = (const float*)d_in[2];
    const float* B2    = (const float*)d_in[3];
    const float* C1    = (const float*)d_in[4];
    const float* C2    = (const float*)d_in[5];
    const float* omega = (const float*)d_in[6];
    const float* onem  = (const float*)d_in[7];
    float* out = (float*)d_out;

    k_prep  <<<512, 256>>>(A, B1, B2, C1, C2);
    k_decode<<<640, 256>>>(onem);          // 2*5*16384 threads
    k_w     <<<2048, 1024>>>();            // (d,p) blocks x (kd,n) threads
    k_gemm  <<<1024, 256>>>();             // 64 kd x 16 p-tiles of 64
    k_asm   <<<1024, 256>>>();             // assembly -> duplicated-pair kernel
    k_conv  <<<1024, 256>>>(x, omega, out);
}

// round 9
// speedup vs baseline: 1.3913x; 1.3913x over previous
#include <cuda_runtime.h>
#include <math.h>

// Problem constants
#define SEQQ   1024      // L_SIDE*L_SIDE
#define BSZ    8
#define EMBED  1024
#define KDIM   64        // kernel_dim = DIRS * N_SSM
#define NDIM   16
#define VPOW   64        // vander power dim
#define R2E    16        // expansion terms per position
#define NR     16384     // R per flow axis (SEQ * R2)
#define HCH    64        // EMBED / N_SSM

// ---------------- scratch (device globals; no allocations) ----------------
__device__ float g_Ls[4 * 1024];        // log2(sigmoid(A))  [a][kd*16+n]
__device__ float g_Bsig[2 * 1024];      // sigmoid(B1/B2)    [c][kd*16+n]
__device__ int   g_E[2 * NR * 4];       // one-hot power indices per (d,r,a)
__device__ int   g_Col[2 * NR];         // B column select (0/1)
__device__ float g_Coef[2 * NR];        // integer coefficient
__device__ float g_w[SEQQ * KDIM * 32]; // w  [p][kd][dn] , dn = d*16+n
__device__ float g_Cc[KDIM * HCH * 32]; // Ccat [kd][h][dn] (x0.25 folded)
__device__ float g_ktmp[HCH * KDIM * SEQQ]; // [h][kd][p]
__device__ float g_ksum[EMBED * SEQQ];  // summed+flipped kernel [e][pos]

__device__ __forceinline__ float ex2_approx(float e) {
    float r; asm("ex2.approx.ftz.f32 %0, %1;" : "=f"(r) : "f"(e)); return r;
}

// ---------------- stage 1+2 merged: prep (sigmoids/logs/Ccat) + decode ----------------
__global__ void k_init(const float* __restrict__ A,
                       const float* __restrict__ B1,
                       const float* __restrict__ B2,
                       const float* __restrict__ C1,
                       const float* __restrict__ C2,
                       const float* __restrict__ M) {
    int bb = blockIdx.x;
    if (bb < 512) {
        int idx = bb * 256 + threadIdx.x;
        if (idx < 4096) {
            float s = 1.0f / (1.0f + expf(-A[idx]));    // A layout (4,64,16)
            g_Ls[idx] = log2f(s);
        } else if (idx < 5120) {
            int t = idx - 4096;
            g_Bsig[t] = 1.0f / (1.0f + expf(-B1[t]));
        } else if (idx < 6144) {
            int t = idx - 5120;
            g_Bsig[1024 + t] = 1.0f / (1.0f + expf(-B2[t]));
        }
        if (idx < KDIM * HCH * 32) {                    // 131072
            int kd = idx >> 11;
            int hh = (idx >> 5) & 63;
            int dn = idx & 31;
            int d = dn >> 4, n = dn & 15;
            const float* C = d ? C2 : C1;
            g_Cc[idx] = 0.25f * C[(hh * 64 + kd) * 16 + n];  // scale=1/sqrt(16)
        }
    } else {
        int t = (bb - 512) * 256 + threadIdx.x;          // (d,a,r) flattened
        if (t >= 2 * 5 * NR) return;
        const float4* m4 = reinterpret_cast<const float4*>(M + (size_t)t * 64);
        int idx = 0; float val = 0.0f;
#pragma unroll
        for (int i = 0; i < 16; i++) {
            float4 v = m4[i];
            if (v.x != 0.0f) { idx = 4 * i + 0; val = v.x; }
            if (v.y != 0.0f) { idx = 4 * i + 1; val = v.y; }
            if (v.z != 0.0f) { idx = 4 * i + 2; val = v.z; }
            if (v.w != 0.0f) { idx = 4 * i + 3; val = v.w; }
        }
        int d   = t / (5 * NR);
        int rem = t - d * (5 * NR);
        int a   = rem / NR;
        int r   = rem - a * NR;
        if (a < 4) {
            g_E[(d * NR + r) * 4 + a] = idx;
        } else {
            g_Col[d * NR + r]  = idx;
            g_Coef[d * NR + r] = val;
        }
    }
}

// ---------------- stage 3: w[d,p,k,n] via MUFU exp2 of summed log-powers ----------------
__global__ void k_w() {
    __shared__ float se[64];
    __shared__ float scoef[16];
    __shared__ int   scol[16];
    int d = blockIdx.x >> 10;
    int p = blockIdx.x & 1023;
    int tid = threadIdx.x;
    if (tid < 64) {
        int r2 = tid >> 2, a = tid & 3;
        se[tid] = (float)g_E[(d * NR + p * 16 + r2) * 4 + a];
    } else if (tid < 80) {
        scoef[tid - 64] = g_Coef[d * NR + p * 16 + (tid - 64)];
    } else if (tid < 96) {
        scol[tid - 80] = g_Col[d * NR + p * 16 + (tid - 80)];
    }
    __syncthreads();
    int kn = tid;                       // 1024 threads = (kd,n)
    float ls0 = g_Ls[kn], ls1 = g_Ls[1024 + kn];
    float ls2 = g_Ls[2048 + kn], ls3 = g_Ls[3072 + kn];
    float b0 = g_Bsig[kn], b1 = g_Bsig[1024 + kn];
    float acc = 0.0f;
#pragma unroll
    for (int r2 = 0; r2 < 16; r2++) {
        float E = se[r2 * 4 + 0] * ls0 + se[r2 * 4 + 1] * ls1
                + se[r2 * 4 + 2] * ls2 + se[r2 * 4 + 3] * ls3;
        float term = ex2_approx(E) * scoef[r2] * (scol[r2] ? b1 : b0);
        acc += term;
    }
    g_w[(p * 64 + (kn >> 4)) * 32 + d * 16 + (kn & 15)] = acc;
}

// ---------------- stage 4: 64 small GEMMs -> ktmp[h][kd][p] ----------------
__global__ __launch_bounds__(256) void k_gemm() {
    __shared__ float Cs[2048];        // [h][dn]  (broadcast reads -> no pad)
    __shared__ float ws[64 * 33];     // [pl][dn] stride-33 pad
    int kd = blockIdx.x & 63;
    int p0 = (blockIdx.x >> 6) * 64;
    int tid = threadIdx.x;
    for (int idx = tid; idx < 2048; idx += 256)
        Cs[idx] = g_Cc[kd * 2048 + idx];
    for (int idx = tid; idx < 2048; idx += 256) {
        int pl = idx >> 5, dn = idx & 31;
        ws[pl * 33 + dn] = g_w[((size_t)(p0 + pl) * 64 + kd) * 32 + dn];
    }
    __syncthreads();
    int tp = tid & 31;                 // p = p0 + tp + 32*i  (bank-disjoint)
    int h0 = (tid >> 5) * 8;
    float acc[2][8];
#pragma unroll
    for (int i = 0; i < 2; i++)
#pragma unroll
        for (int j = 0; j < 8; j++) acc[i][j] = 0.0f;
#pragma unroll 8
    for (int dn = 0; dn < 32; dn++) {
        float cv[8];
#pragma unroll
        for (int j = 0; j < 8; j++) cv[j] = Cs[(h0 + j) * 32 + dn];
#pragma unroll
        for (int i = 0; i < 2; i++) {
            float wv = ws[(tp + 32 * i) * 33 + dn];
#pragma unroll
            for (int j = 0; j < 8; j++) acc[i][j] += wv * cv[j];
        }
    }
#pragma unroll
    for (int j = 0; j < 8; j++)
#pragma unroll
        for (int i = 0; i < 2; i++)
            g_ktmp[((h0 + j) * 64 + kd) * 1024 + p0 + tp + 32 * i] = acc[i][j];
}

// ---------------- stage 5: boundary scale + 4-direction flip-sum ----------------
__device__ __forceinline__ float bscale(int i, int j) {
    // row0 x2, col0 x2, corner /4 => corner net 1, edges 2, interior 1
    return ((i == 0) != (j == 0)) ? 2.0f : 1.0f;
}
__global__ void k_asm() {
    int e = blockIdx.x;
    int h = e >> 4, ns = e & 15;
    const float* b0 = g_ktmp + (h * 64 +  0 + ns) * 1024;
    const float* b1 = g_ktmp + (h * 64 + 16 + ns) * 1024;
    const float* b2 = g_ktmp + (h * 64 + 32 + ns) * 1024;
    const float* b3 = g_ktmp + (h * 64 + 48 + ns) * 1024;
    for (int pos = threadIdx.x; pos < 1024; pos += 256) {
        int i = pos >> 5, j = pos & 31;
        int fi = 31 - i, fj = 31 - j;
        float v = bscale(i,  j)  * b0[i  * 32 + j ]
                + bscale(fi, j)  * b1[fi * 32 + j ]
                + bscale(i,  fj) * b2[i  * 32 + fj]
                + bscale(fi, fj) * b3[fi * 32 + fj];
        g_ksum[e * 1024 + pos] = v;
    }
}

// ---------------- stage 6: causal 2D conv (complementary-mask packed) ----------------
// Warp = (channel e, batch pair A=b0, B=b0+1). Prepass: all lanes do image-A
// shift 0 on their own row. Main loop di=1..32: lanes >= di continue image-A
// row `lane` at shift di; lanes < di work image-B row (31-lane) at shift
// (32-di). Active masks are exact complements -> zero idle lanes; kernel rows
// (di for A, 32-di for B) are warp-uniform-per-group -> 2-address LDG.128.
// Lane lane==di-1 switches A->B at iteration di: flush A row into the A-image
// slot (32-di) freed this very iteration, zero accumulators. Residual is added
// at writeback from a fresh coalesced x read. Both result images end up
// row-reversed in smem (row r at slot 31-r).
__global__ __launch_bounds__(64) void k_conv(const float* __restrict__ x,
                                             const float* __restrict__ omega,
                                             float* __restrict__ out) {
    __shared__ float sx[2 * 2112];     // 2 channels x (2 images x 32x33)
    int gb = blockIdx.x;               // 2048 = 4 bpairs x 512 e-pairs
    int bp = gb >> 9;
    int e0 = (gb & 511) * 2;
    int b0 = bp * 2;
    int tid = threadIdx.x;
    int ww = tid >> 5, lane = tid & 31;

    // stage x: x[pos][b][e] -> sx[ee][bs][row][q]
    for (int idx = tid; idx < 4096; idx += 64) {
        int ee = idx & 1, bs = (idx >> 1) & 1, pos = idx >> 2;
        int row = pos >> 5, q = pos & 31;
        sx[ee * 2112 + bs * 1056 + row * 33 + q] =
            x[(size_t)(pos * 8 + b0 + bs) * 1024 + e0 + ee];
    }
    __syncthreads();

    float* xA = sx + ww * 2112;
    float* xB = xA + 1056;
    const float* kg = g_ksum + (size_t)(e0 + ww) * 1024;  // 4KB, L1-resident

    float y[32], xr[32], kr[32];

    // prepass: image A, shift 0, own row
    {
        const float* px = xA + lane * 33;
#pragma unroll
        for (int c = 0; c < 32; c++) xr[c] = px[c];
        const float4* k4 = reinterpret_cast<const float4*>(kg);
#pragma unroll
        for (int c = 0; c < 8; c++) {
            float4 v = k4[c];
            kr[4*c] = v.x; kr[4*c+1] = v.y; kr[4*c+2] = v.z; kr[4*c+3] = v.w;
        }
#pragma unroll
        for (int j = 0; j < 32; j++) y[j] = kr[0] * xr[j];
#pragma unroll
        for (int dj = 1; dj < 32; dj++) {
            float kv = kr[dj];
#pragma unroll
            for (int j = dj; j < 32; j++) y[j] = fmaf(kv, xr[j - dj], y[j]);
        }
    }

    for (int di = 1; di <= 32; di++) {
        bool sw = (lane == di - 1);
        if (sw) {
            // flush completed A row `lane` into freed slot 32-di (= 31-lane)
            float* dst = xA + (32 - di) * 33;
#pragma unroll
            for (int j = 0; j < 32; j++) dst[j] = y[j];
#pragma unroll
            for (int j = 0; j < 32; j++) y[j] = 0.0f;
        }
        __syncwarp();                  // order flush STS vs other lanes' LDS
        bool isA = (lane >= di);
        int xrow = isA ? (lane - di) : (di - 1 - lane);
        const float* px = (isA ? xA : xB) + xrow * 33;
        int krow = isA ? di : (32 - di);     // di=32: all lanes B, krow=0
        const float4* k4 = reinterpret_cast<const float4*>(kg + krow * 32);
#pragma unroll
        for (int c = 0; c < 32; c++) xr[c] = px[c];
#pragma unroll
        for (int c = 0; c < 8; c++) {
            float4 v = k4[c];
            kr[4*c] = v.x; kr[4*c+1] = v.y; kr[4*c+2] = v.z; kr[4*c+3] = v.w;
        }
#pragma unroll
        for (int dj = 0; dj < 32; dj++) {
            float kv = kr[dj];
#pragma unroll
            for (int j = dj; j < 32; j++) y[j] = fmaf(kv, xr[j - dj], y[j]);
        }
    }
    __syncwarp();
    // lane holds B row 31-lane -> slot lane (same reversed convention as A)
    {
        float* dst = xB + lane * 33;
#pragma unroll
        for (int j = 0; j < 32; j++) dst[j] = y[j];
    }
    __syncthreads();

    // coalesced writeback + residual (fresh x read); rows stored reversed
    float om0 = omega[e0], om1 = omega[e0 + 1];
    for (int idx = tid; idx < 4096; idx += 64) {
        int ee = idx & 1, bs = (idx >> 1) & 1, pos = idx >> 2;
        int row = pos >> 5, q = pos & 31;
        float om = ee ? om1 : om0;
        size_t ga = (size_t)(pos * 8 + b0 + bs) * 1024 + e0 + ee;
        out[ga] = sx[ee * 2112 + bs * 1056 + (31 - row) * 33 + q] + om * x[ga];
    }
}

// ---------------- launch ----------------
extern "C" void kernel_launch(void* const* d_in, const int* in_sizes, int n_in,
                              void* d_out, int out_size) {
    const float* x     = (const float*)d_in[0];
    const float* A     = (const float*)d_in[1];
    const float* B1    = (const float*)d_in[2];
    const float* B2    = (const float*)d_in[3];
    const float* C1    = (const float*)d_in[4];
    const float* C2    = (const float*)d_in[5];
    const float* omega = (const float*)d_in[6];
    const float* onem  = (const float*)d_in[7];
    float* out = (float*)d_out;

    k_init  <<<1152, 256>>>(A, B1, B2, C1, C2, onem); // prep(512) + decode(640)
    k_w     <<<2048, 1024>>>();            // (d,p) blocks x (kd,n) threads
    k_gemm  <<<1024, 256>>>();             // 64 kd x 16 p-tiles of 64
    k_asm   <<<1024, 256>>>();             // per-embed-channel assembly
    k_conv  <<<2048, 64>>>(x, omega, out); // complementary-mask packed conv
}